// round 14
// baseline (speedup 1.0000x reference)
#include <cuda_runtime.h>
#include <cuda_bf16.h>
#include <cuda_fp16.h>
#include <cstdint>

#define NMAX   100000
#define EMAX   3200000
#define FDIM   512
#define HID    32
#define C3     96          // 3 views * 32

// ---------------- device scratch (static: no allocation allowed) ----------------
__device__ int    g_is64;
__device__ float4 g_dinv4[NMAX];          // {d0,d1,d2,-} packed
__device__ int    g_cnt[NMAX];
__device__ int    g_off[NMAX + 1];
__device__ int    g_cursor[NMAX];
__device__ int    g_bsum[1024];
__device__ float2 g_csr[EMAX];            // {w, src | m1bit<<30 | m2bit<<31}
__device__ uint32_t g_WHt[(FDIM / 2) * C3];   // bf16-hi k-pairs, [k2][n]
__device__ uint32_t g_WLt[(FDIM / 2) * C3];   // bf16-lo k-pairs, [k2][n]
__device__ float  g_H[(size_t)NMAX * C3];     // layer-1 features (dinv-scaled after k_prep)
__device__ float  g_H2[(size_t)NMAX * C3];    // layer-2 features (written pre-scaled)
__device__ __half g_Hh[(size_t)NMAX * C3];    // fp16 gather copy of scaled H
__device__ __half g_H2h[(size_t)NMAX * C3];   // fp16 gather copy of scaled H2

// ---------------- dtype sniff: int64 edge_index has all-zero high words ----------
__global__ void k_detect(const unsigned int* __restrict__ wbuf, long long nwords) {
    __shared__ int s;
    if (threadIdx.x == 0) s = 1;
    __syncthreads();
    int ok = 1;
    for (long long i = threadIdx.x; i < 2048; i += blockDim.x) {
        long long wi = 2 * i + 1;
        if (wi < nwords && wbuf[wi] != 0u) ok = 0;
    }
    if (!ok) atomicAnd(&s, 0);
    __syncthreads();
    if (threadIdx.x == 0) g_is64 = s;
}

__device__ __forceinline__ int2 read_edge(const void* ei, int E, int e, int is64) {
    if (is64) {
        const long long* p = (const long long*)ei;
        return make_int2((int)p[e], (int)p[E + e]);
    } else {
        const int* p = (const int*)ei;
        return make_int2(p[e], p[E + e]);
    }
}

__global__ void k_init(int N) {
    int i = blockIdx.x * blockDim.x + threadIdx.x;
    if (i < N) g_cnt[i] = 0;
}

// -------- fold feature masks into W1; bf16 hi/lo split, k-pair-packed [k2][n] --------
__global__ void k_wcat(const float* __restrict__ W1,
                       const float* __restrict__ fm1, const float* __restrict__ fm2) {
    int i = blockIdx.x * blockDim.x + threadIdx.x;
    if (i >= C3 * FDIM) return;
    int nn = i / FDIM, k = i - nn * FDIM;
    int v = nn >> 5, c = nn & 31;
    float m = (v == 0) ? 1.0f : (v == 1 ? fm1[k] : fm2[k]);
    float val = W1[k * HID + c] * m;
    __nv_bfloat16 h = __float2bfloat16(val);
    __nv_bfloat16 l = __float2bfloat16(val - __bfloat162float(h));
    int addr = ((k >> 1) * C3 + nn) * 2 + (k & 1);
    ((__nv_bfloat16*)g_WHt)[addr] = h;
    ((__nv_bfloat16*)g_WLt)[addr] = l;
}

// ======= HMMA GEMM, cp.async pipelined: H[N,96] = x[N,512] @ Wcat (3-term bf16 split) =======
__device__ __forceinline__ void mma16816(float* d, const uint32_t* a, const uint32_t* b) {
    asm volatile("mma.sync.aligned.m16n8k16.row.col.f32.bf16.bf16.f32 "
        "{%0,%1,%2,%3}, {%4,%5,%6,%7}, {%8,%9}, {%0,%1,%2,%3};"
        : "+f"(d[0]), "+f"(d[1]), "+f"(d[2]), "+f"(d[3])
        : "r"(a[0]), "r"(a[1]), "r"(a[2]), "r"(a[3]), "r"(b[0]), "r"(b[1]));
}
__device__ __forceinline__ uint32_t smem_u32p(const void* p) {
    uint32_t a;
    asm("{ .reg .u64 t; cvta.to.shared.u64 t, %1; cvt.u32.u64 %0, t; }" : "=r"(a) : "l"(p));
    return a;
}
__device__ __forceinline__ void cpa16(uint32_t dst, const void* src, int nbytes) {
    asm volatile("cp.async.cg.shared.global [%0], [%1], 16, %2;"
                 :: "r"(dst), "l"(src), "r"(nbytes));
}
#define CPA_COMMIT() asm volatile("cp.async.commit_group;" ::: "memory")
#define CPA_WAIT0()  asm volatile("cp.async.wait_group 0;" ::: "memory")

// split 2 fp32 -> packed bf16 hi pair + lo pair
__device__ __forceinline__ void cvt_split(float vx, float vy, uint32_t& hi, uint32_t& lo) {
    __nv_bfloat162 h2 = __float22bfloat162_rn(make_float2(vx, vy));
    hi = *(uint32_t*)&h2;
    float hx = __uint_as_float((hi & 0xFFFFu) << 16);
    float hy = __uint_as_float(hi & 0xFFFF0000u);
    __nv_bfloat162 l2 = __float22bfloat162_rn(make_float2(vx - hx, vy - hy));
    lo = *(uint32_t*)&l2;
}

#define TM     256
#define KC     64
#define A_STRF 72                        // fp32 per A smem row (64 + 8 pad), 288 B
#define A_STG  (256 * 288)               // 73728 B per stage
#define B_ROW  416                       // 104 u32 * 4 B per B smem row
#define B_HALF 13312                     // 32 rows * 416
#define B_STG  (2 * B_HALF)              // hi + lo
#define SM_A   0
#define SM_B   (2 * A_STG)               // 147456
#define SM_TOT (SM_B + 2 * B_STG)        // 200704

__global__ __launch_bounds__(512, 1) void k_gemm(const float* __restrict__ x, int N) {
    extern __shared__ char smem[];
    uint32_t sb = smem_u32p(smem);
    int tid = threadIdx.x, wid = tid >> 5, lane = tid & 31;
    int g = lane >> 2, tig = lane & 3;
    int warp_m = wid >> 1, warp_n = wid & 1;       // 8 x 2
    int row_w = warp_m * 32, col_w = warp_n * 48;
    int row0 = blockIdx.x * TM;

    float acc[2][6][4];
    #pragma unroll
    for (int a = 0; a < 2; a++)
        #pragma unroll
        for (int b = 0; b < 6; b++)
            #pragma unroll
            for (int c = 0; c < 4; c++) acc[a][b][c] = 0.0f;

    #define ISSUE_CHUNK(CH, STG) do {                                              \
        int _ch = (CH), _st = (STG);                                               \
        _Pragma("unroll")                                                          \
        for (int i = 0; i < 8; i++) {                                              \
            int p = tid + i * 512;                                                 \
            int row = p >> 4, cq = p & 15;                                         \
            int r = row0 + row;                                                    \
            int ok = (r < N) ? 16 : 0;                                             \
            int rc = (r < N) ? r : (N - 1);                                        \
            const float* src = &x[(size_t)rc * FDIM + _ch * KC + cq * 4];          \
            cpa16(sb + SM_A + _st * A_STG + row * 288 + cq * 16, src, ok);         \
        }                                                                          \
        _Pragma("unroll")                                                          \
        for (int i = 0; i < 3; i++) {                                              \
            int p = tid + i * 512;                                                 \
            int half = p >= 768;                                                   \
            int q = p - half * 768;                                                \
            int k2 = q / 24, c16 = q - k2 * 24;                                    \
            const uint32_t* src = (half ? g_WLt : g_WHt)                           \
                                  + (_ch * 32 + k2) * C3 + c16 * 4;                \
            cpa16(sb + SM_B + _st * B_STG + half * B_HALF + k2 * B_ROW + c16 * 16, \
                  src, 16);                                                        \
        }                                                                          \
        CPA_COMMIT();                                                              \
    } while (0)

    ISSUE_CHUNK(0, 0);

    const float* As;
    const uint32_t *Bhs, *Bls;
    for (int ch = 0; ch < FDIM / KC; ch++) {
        int st = ch & 1;
        CPA_WAIT0();
        __syncthreads();
        if (ch + 1 < FDIM / KC) ISSUE_CHUNK(ch + 1, (ch + 1) & 1);

        As  = (const float*)(smem + SM_A + st * A_STG);
        Bhs = (const uint32_t*)(smem + SM_B + st * B_STG);
        Bls = (const uint32_t*)(smem + SM_B + st * B_STG + B_HALF);

        #pragma unroll
        for (int kk = 0; kk < KC / 16; kk++) {
            int kb = kk * 16;
            uint32_t ah[2][4], al[2][4], bh[6][2], bl[6][2];
            #pragma unroll
            for (int mt = 0; mt < 2; mt++) {
                int r = row_w + mt * 16 + g;
                float2 v0 = *(const float2*)&As[r * A_STRF + kb + 2 * tig];
                float2 v1 = *(const float2*)&As[(r + 8) * A_STRF + kb + 2 * tig];
                float2 v2 = *(const float2*)&As[r * A_STRF + kb + 8 + 2 * tig];
                float2 v3 = *(const float2*)&As[(r + 8) * A_STRF + kb + 8 + 2 * tig];
                cvt_split(v0.x, v0.y, ah[mt][0], al[mt][0]);
                cvt_split(v1.x, v1.y, ah[mt][1], al[mt][1]);
                cvt_split(v2.x, v2.y, ah[mt][2], al[mt][2]);
                cvt_split(v3.x, v3.y, ah[mt][3], al[mt][3]);
            }
            #pragma unroll
            for (int nt = 0; nt < 6; nt++) {
                int c = col_w + nt * 8 + g;
                bh[nt][0] = Bhs[(kk * 8 + tig) * 104 + c];
                bh[nt][1] = Bhs[(kk * 8 + tig + 4) * 104 + c];
                bl[nt][0] = Bls[(kk * 8 + tig) * 104 + c];
                bl[nt][1] = Bls[(kk * 8 + tig + 4) * 104 + c];
            }
            #pragma unroll
            for (int mt = 0; mt < 2; mt++)
                #pragma unroll
                for (int nt = 0; nt < 6; nt++) {
                    mma16816(acc[mt][nt], ah[mt], bh[nt]);
                    mma16816(acc[mt][nt], ah[mt], bl[nt]);
                    mma16816(acc[mt][nt], al[mt], bh[nt]);
                }
        }
        __syncthreads();
    }

    #pragma unroll
    for (int mt = 0; mt < 2; mt++) {
        int r = row0 + row_w + mt * 16 + g;
        #pragma unroll
        for (int nt = 0; nt < 6; nt++) {
            int c = col_w + nt * 8 + 2 * tig;
            if (r < N)
                *(float2*)&g_H[(size_t)r * C3 + c] = make_float2(acc[mt][nt][0], acc[mt][nt][1]);
            if (r + 8 < N)
                *(float2*)&g_H[(size_t)(r + 8) * C3 + c] = make_float2(acc[mt][nt][2], acc[mt][nt][3]);
        }
    }
    #undef ISSUE_CHUNK
}

// ---------------- count only ----------------
__global__ void k_cnt(const void* ei, int E) {
    int e = blockIdx.x * blockDim.x + threadIdx.x;
    if (e >= E) return;
    int dst;
    if (g_is64) dst = (int)((const long long*)ei)[E + e];
    else        dst = ((const int*)ei)[E + e];
    atomicAdd(&g_cnt[dst], 1);
}

// ---------------- exclusive prefix sum of g_cnt -> g_off ----------------
__global__ void k_scan1(int N) {
    __shared__ int warpsum[16];
    int b = blockIdx.x, t = threadIdx.x;
    int i = b * 512 + t;
    int v = (i < N) ? g_cnt[i] : 0;
    int lane = t & 31, wid = t >> 5;
    int x = v;
    #pragma unroll
    for (int o = 1; o < 32; o <<= 1) {
        int y = __shfl_up_sync(0xFFFFFFFFu, x, o);
        if (lane >= o) x += y;
    }
    if (lane == 31) warpsum[wid] = x;
    __syncthreads();
    if (wid == 0) {
        int ws = (lane < 16) ? warpsum[lane] : 0;
        #pragma unroll
        for (int o = 1; o < 16; o <<= 1) {
            int y = __shfl_up_sync(0xFFFFFFFFu, ws, o);
            if (lane >= o) ws += y;
        }
        if (lane < 16) warpsum[lane] = ws;
    }
    __syncthreads();
    int base = (wid > 0) ? warpsum[wid - 1] : 0;
    if (i < N) g_off[i] = base + x - v;
    if (t == 511) g_bsum[b] = base + x;
}

__global__ void k_scan2(int NB) {
    __shared__ int sh[1024];
    int t = threadIdx.x;
    sh[t] = (t < NB) ? g_bsum[t] : 0;
    __syncthreads();
    for (int o = 1; o < 1024; o <<= 1) {
        int v = sh[t];
        int add = (t >= o) ? sh[t - o] : 0;
        __syncthreads();
        sh[t] = v + add;
        __syncthreads();
    }
    if (t < NB) g_bsum[t] = (t > 0) ? sh[t - 1] : 0;
}

__global__ void k_scan3(int N, int E) {
    int i = blockIdx.x * blockDim.x + threadIdx.x;
    if (i < N) {
        int o = g_off[i] + g_bsum[i >> 9];
        g_off[i] = o;
        g_cursor[i] = o;
    }
    if (i == 0) g_off[N] = E;
}

// ------- scatter edges into packed CSR: {w, src | m1bit<<30 | m2bit<<31} -------
__global__ void k_scatter(const void* ei, const float* __restrict__ w,
                          const float* __restrict__ m1, const float* __restrict__ m2, int E) {
    int e = blockIdx.x * blockDim.x + threadIdx.x;
    if (e >= E) return;
    int2 sd = read_edge(ei, E, e, g_is64);
    float we = w[e];
    unsigned int packed = (unsigned int)sd.x;
    if (m1[e] > 0.5f) packed |= 0x40000000u;
    if (m2[e] > 0.5f) packed |= 0x80000000u;
    int p = atomicAdd(&g_cursor[sd.y], 1);
    g_csr[p] = make_float2(we, __uint_as_float(packed));
}

// ---------------- degrees from CSR segments (no atomics), dinv ----------------
__global__ void k_deg2(int N) {
    int warp = (blockIdx.x * blockDim.x + threadIdx.x) >> 5;
    int lane = threadIdx.x & 31;
    if (warp >= N) return;
    int beg = g_off[warp], end = g_off[warp + 1];
    float s0 = 0.f, s1 = 0.f, s2 = 0.f;
    for (int p = beg + lane; p < end; p += 32) {
        float2 md = g_csr[p];
        unsigned int pk = __float_as_uint(md.y);
        s0 += md.x;
        if (pk & 0x40000000u) s1 += md.x;
        if (pk & 0x80000000u) s2 += md.x;
    }
    #pragma unroll
    for (int o = 16; o; o >>= 1) {
        s0 += __shfl_xor_sync(0xFFFFFFFFu, s0, o);
        s1 += __shfl_xor_sync(0xFFFFFFFFu, s1, o);
        s2 += __shfl_xor_sync(0xFFFFFFFFu, s2, o);
    }
    if (lane == 0) {
        g_dinv4[warp] = make_float4(rsqrtf(s0 + 1.0f), rsqrtf(s1 + 1.0f), rsqrtf(s2 + 1.0f), 0.f);
    }
}

// ---- scale H by dinv per view (in place) + write fp16 gather copy ----
__global__ void k_prep(int N) {
    int warp = (blockIdx.x * blockDim.x + threadIdx.x) >> 5;
    int lane = threadIdx.x & 31;
    if (warp >= N) return;
    float4 dd = g_dinv4[warp];
    size_t o = (size_t)warp * C3;
    float v0 = g_H[o + lane]      * dd.x;
    float v1 = g_H[o + lane + 32] * dd.y;
    float v2 = g_H[o + lane + 64] * dd.z;
    g_H[o + lane]      = v0;
    g_H[o + lane + 32] = v1;
    g_H[o + lane + 64] = v2;
    g_Hh[o + lane]      = __float2half(v0);
    g_Hh[o + lane + 32] = __float2half(v1);
    g_Hh[o + lane + 64] = __float2half(v2);
}

// ---- agg body over PRE-SCALED fp16 H': a_v = sum_e H'[src][v]·w_v(e) ----
__device__ __forceinline__ void agg_body(const __half* __restrict__ Hsrc, int beg, int end,
                                         int lane, float& a0, float& a1, float& a2) {
    for (int base = beg; base < end; base += 32) {
        int cnt = end - base; if (cnt > 32) cnt = 32;
        float2 md = (lane < cnt) ? g_csr[base + lane] : make_float2(0.f, 0.f);
        unsigned int pk = __float_as_uint(md.y);
        float w = md.x;
        int j = 0;
        #pragma unroll 1
        for (; j + 4 <= cnt; j += 4) {
            unsigned int p0 = __shfl_sync(0xFFFFFFFFu, pk, j);
            unsigned int p1 = __shfl_sync(0xFFFFFFFFu, pk, j + 1);
            unsigned int p2 = __shfl_sync(0xFFFFFFFFu, pk, j + 2);
            unsigned int p3 = __shfl_sync(0xFFFFFFFFu, pk, j + 3);
            float w0 = __shfl_sync(0xFFFFFFFFu, w, j);
            float w1 = __shfl_sync(0xFFFFFFFFu, w, j + 1);
            float w2 = __shfl_sync(0xFFFFFFFFu, w, j + 2);
            float w3 = __shfl_sync(0xFFFFFFFFu, w, j + 3);
            const __half* h0 = &Hsrc[(size_t)(p0 & 0x3FFFFFFFu) * C3];
            const __half* h1 = &Hsrc[(size_t)(p1 & 0x3FFFFFFFu) * C3];
            const __half* h2 = &Hsrc[(size_t)(p2 & 0x3FFFFFFFu) * C3];
            const __half* h3 = &Hsrc[(size_t)(p3 & 0x3FFFFFFFu) * C3];
            float v00 = __half2float(h0[lane]), v01 = __half2float(h0[lane + 32]), v02 = __half2float(h0[lane + 64]);
            float v10 = __half2float(h1[lane]), v11 = __half2float(h1[lane + 32]), v12 = __half2float(h1[lane + 64]);
            float v20 = __half2float(h2[lane]), v21 = __half2float(h2[lane + 32]), v22 = __half2float(h2[lane + 64]);
            float v30 = __half2float(h3[lane]), v31 = __half2float(h3[lane + 32]), v32 = __half2float(h3[lane + 64]);
            a0 += v00 * w0 + v10 * w1 + v20 * w2 + v30 * w3;
            a1 += v01 * ((p0 & 0x40000000u) ? w0 : 0.f)
                + v11 * ((p1 & 0x40000000u) ? w1 : 0.f)
                + v21 * ((p2 & 0x40000000u) ? w2 : 0.f)
                + v31 * ((p3 & 0x40000000u) ? w3 : 0.f);
            a2 += v02 * ((p0 & 0x80000000u) ? w0 : 0.f)
                + v12 * ((p1 & 0x80000000u) ? w1 : 0.f)
                + v22 * ((p2 & 0x80000000u) ? w2 : 0.f)
                + v32 * ((p3 & 0x80000000u) ? w3 : 0.f);
        }
        for (; j < cnt; j++) {
            unsigned int pj = __shfl_sync(0xFFFFFFFFu, pk, j);
            float wj = __shfl_sync(0xFFFFFFFFu, w, j);
            const __half* hr = &Hsrc[(size_t)(pj & 0x3FFFFFFFu) * C3];
            a0 += __half2float(hr[lane]) * wj;
            a1 += __half2float(hr[lane + 32]) * ((pj & 0x40000000u) ? wj : 0.f);
            a2 += __half2float(hr[lane + 64]) * ((pj & 0x80000000u) ? wj : 0.f);
        }
    }
}

// ---- fused layer-1: agg + self + bias + relu + W2 matmul; writes PRE-SCALED H2' + fp16 copy ----
__global__ void k_agg1mid(const float* __restrict__ b1, const float* __restrict__ W2, int N) {
    __shared__ float Ws[HID * HID];
    int t = threadIdx.x;
    for (int l = t; l < HID * HID; l += blockDim.x) Ws[l] = W2[l];
    __syncthreads();
    int warp = (blockIdx.x * blockDim.x + t) >> 5;
    int lane = t & 31;
    if (warp >= N) return;
    float4 dd = g_dinv4[warp];
    float a0 = 0.f, a1 = 0.f, a2 = 0.f;
    agg_body(g_Hh, g_off[warp], g_off[warp + 1], lane, a0, a1, a2);

    size_t o = (size_t)warp * C3;
    float bb = b1[lane];
    float z0 = fmaxf(dd.x * (a0 + g_H[o + lane])      + bb, 0.0f);
    float z1 = fmaxf(dd.y * (a1 + g_H[o + lane + 32]) + bb, 0.0f);
    float z2 = fmaxf(dd.z * (a2 + g_H[o + lane + 64]) + bb, 0.0f);
    float o0 = 0.f, o1 = 0.f, o2 = 0.f;
    #pragma unroll
    for (int k = 0; k < HID; k++) {
        float wv = Ws[k * HID + lane];
        o0 += __shfl_sync(0xFFFFFFFFu, z0, k) * wv;
        o1 += __shfl_sync(0xFFFFFFFFu, z1, k) * wv;
        o2 += __shfl_sync(0xFFFFFFFFu, z2, k) * wv;
    }
    float s0 = o0 * dd.x, s1 = o1 * dd.y, s2 = o2 * dd.z;
    g_H2[o + lane]      = s0;
    g_H2[o + lane + 32] = s1;
    g_H2[o + lane + 64] = s2;
    g_H2h[o + lane]      = __float2half(s0);
    g_H2h[o + lane + 32] = __float2half(s1);
    g_H2h[o + lane + 64] = __float2half(s2);
}

// ---- fused layer-2: agg + self + bias + relu + permute -> d_out ----
__global__ void k_agg2post(const float* __restrict__ b2, float* __restrict__ out, int N) {
    int warp = (blockIdx.x * blockDim.x + threadIdx.x) >> 5;
    int lane = threadIdx.x & 31;
    if (warp >= N) return;
    float4 dd = g_dinv4[warp];
    float a0 = 0.f, a1 = 0.f, a2 = 0.f;
    agg_body(g_H2h, g_off[warp], g_off[warp + 1], lane, a0, a1, a2);

    size_t o = (size_t)warp * C3;
    float bb = b2[lane];
    float r0 = fmaxf(dd.x * (a0 + g_H2[o + lane])      + bb, 0.0f);
    float r1 = fmaxf(dd.y * (a1 + g_H2[o + lane + 32]) + bb, 0.0f);
    float r2 = fmaxf(dd.z * (a2 + g_H2[o + lane + 64]) + bb, 0.0f);
    out[((size_t)0 * N + warp) * HID + lane] = r0;
    out[((size_t)1 * N + warp) * HID + lane] = r1;
    out[((size_t)2 * N + warp) * HID + lane] = r2;
}

// =====================================================================
extern "C" void kernel_launch(void* const* d_in, const int* in_sizes, int n_in,
                              void* d_out, int out_size) {
    const float* x   = (const float*)d_in[0];
    const void*  ei  = d_in[1];
    const float* w   = (const float*)d_in[2];
    const float* m1  = (const float*)d_in[3];
    const float* m2  = (const float*)d_in[4];
    const float* fm1 = (const float*)d_in[5];
    const float* fm2 = (const float*)d_in[6];
    const float* W1  = (const float*)d_in[7];
    const float* b1  = (const float*)d_in[8];
    const float* W2  = (const float*)d_in[9];
    const float* b2  = (const float*)d_in[10];

    int E = in_sizes[2];
    int F = in_sizes[5];
    int N = in_sizes[0] / F;

    // lazily created host-side objects (first call = uncaptured correctness run)
    static cudaStream_t s2 = nullptr;
    static cudaEvent_t ev_fork = nullptr, ev_join = nullptr;
    static int attr_done = 0;
    if (!attr_done) {
        cudaFuncSetAttribute(k_gemm, cudaFuncAttributeMaxDynamicSharedMemorySize, SM_TOT);
        cudaStreamCreateWithFlags(&s2, cudaStreamNonBlocking);
        cudaEventCreateWithFlags(&ev_fork, cudaEventDisableTiming);
        cudaEventCreateWithFlags(&ev_join, cudaEventDisableTiming);
        attr_done = 1;
    }

    // ---- fork immediately; edge pipeline (incl. detect) on s2 ----
    cudaEventRecord(ev_fork, 0);
    cudaStreamWaitEvent(s2, ev_fork, 0);

    k_detect<<<1, 256, 0, s2>>>((const unsigned int*)ei, (long long)2 * E);
    k_init<<<(N + 255) / 256, 256, 0, s2>>>(N);
    k_cnt<<<(E + 255) / 256, 256, 0, s2>>>(ei, E);
    int NB = (N + 511) / 512;
    k_scan1<<<NB, 512, 0, s2>>>(N);
    k_scan2<<<1, 1024, 0, s2>>>(NB);
    k_scan3<<<(N + 511) / 512, 512, 0, s2>>>(N, E);
    k_scatter<<<(E + 255) / 256, 256, 0, s2>>>(ei, w, m1, m2, E);
    k_deg2<<<(int)(((long long)N * 32 + 255) / 256), 256, 0, s2>>>(N);
    cudaEventRecord(ev_join, s2);

    // ---- origin stream: GEMM chain (overlaps edge pipeline) ----
    k_wcat<<<(C3 * FDIM + 255) / 256, 256>>>(W1, fm1, fm2);
    k_gemm<<<(N + TM - 1) / TM, 512, SM_TOT>>>(x, N);

    // ---- join, prep (scale + fp16 copy), then fused agg layers ----
    cudaStreamWaitEvent(0, ev_join, 0);
    int nwb = (int)(((long long)N * 32 + 255) / 256);
    k_prep<<<nwb, 256>>>(N);
    k_agg1mid<<<nwb, 256>>>(b1, W2, N);
    k_agg2post<<<nwb, 256>>>(b2, (float*)d_out, N);
}

// round 15
// speedup vs baseline: 1.4972x; 1.4972x over previous
#include <cuda_runtime.h>
#include <cuda_bf16.h>
#include <cstdint>

#define NMAX   100000
#define EMAX   3200000
#define FDIM   512
#define HID    32
#define C3     96          // 3 views * 32

// ---------------- device scratch (static: no allocation allowed) ----------------
__device__ int    g_is64;
__device__ float4 g_dinv4[NMAX];          // {d0,d1,d2,-} packed
__device__ int    g_cnt[NMAX];
__device__ int    g_off[NMAX + 1];
__device__ int    g_cursor[NMAX];
__device__ int    g_bsum[1024];
__device__ float2 g_csr[EMAX];            // {w, src | m1bit<<30 | m2bit<<31}
__device__ uint32_t g_WHt[(FDIM / 2) * C3];   // bf16-hi k-pairs, [k2][n]
__device__ uint32_t g_WLt[(FDIM / 2) * C3];   // bf16-lo k-pairs, [k2][n]
__device__ float  g_H[(size_t)NMAX * C3];     // layer-1 features (dinv-scaled after k_scaleH)
__device__ float  g_H2[(size_t)NMAX * C3];    // layer-2 features (written pre-scaled)

// ---------------- dtype sniff: int64 edge_index has all-zero high words ----------
__global__ void k_detect(const unsigned int* __restrict__ wbuf, long long nwords) {
    __shared__ int s;
    if (threadIdx.x == 0) s = 1;
    __syncthreads();
    int ok = 1;
    for (long long i = threadIdx.x; i < 2048; i += blockDim.x) {
        long long wi = 2 * i + 1;
        if (wi < nwords && wbuf[wi] != 0u) ok = 0;
    }
    if (!ok) atomicAnd(&s, 0);
    __syncthreads();
    if (threadIdx.x == 0) g_is64 = s;
}

__device__ __forceinline__ int2 read_edge(const void* ei, int E, int e, int is64) {
    if (is64) {
        const long long* p = (const long long*)ei;
        return make_int2((int)p[e], (int)p[E + e]);
    } else {
        const int* p = (const int*)ei;
        return make_int2(p[e], p[E + e]);
    }
}

__global__ void k_init(int N) {
    int i = blockIdx.x * blockDim.x + threadIdx.x;
    if (i < N) g_cnt[i] = 0;
}

// -------- fold feature masks into W1; bf16 hi/lo split, k-pair-packed [k2][n] --------
__global__ void k_wcat(const float* __restrict__ W1,
                       const float* __restrict__ fm1, const float* __restrict__ fm2) {
    int i = blockIdx.x * blockDim.x + threadIdx.x;
    if (i >= C3 * FDIM) return;
    int nn = i / FDIM, k = i - nn * FDIM;
    int v = nn >> 5, c = nn & 31;
    float m = (v == 0) ? 1.0f : (v == 1 ? fm1[k] : fm2[k]);
    float val = W1[k * HID + c] * m;
    __nv_bfloat16 h = __float2bfloat16(val);
    __nv_bfloat16 l = __float2bfloat16(val - __bfloat162float(h));
    int addr = ((k >> 1) * C3 + nn) * 2 + (k & 1);
    ((__nv_bfloat16*)g_WHt)[addr] = h;
    ((__nv_bfloat16*)g_WLt)[addr] = l;
}

// ======= HMMA GEMM, cp.async pipelined: H[N,96] = x[N,512] @ Wcat (3-term bf16 split) =======
__device__ __forceinline__ void mma16816(float* d, const uint32_t* a, const uint32_t* b) {
    asm volatile("mma.sync.aligned.m16n8k16.row.col.f32.bf16.bf16.f32 "
        "{%0,%1,%2,%3}, {%4,%5,%6,%7}, {%8,%9}, {%0,%1,%2,%3};"
        : "+f"(d[0]), "+f"(d[1]), "+f"(d[2]), "+f"(d[3])
        : "r"(a[0]), "r"(a[1]), "r"(a[2]), "r"(a[3]), "r"(b[0]), "r"(b[1]));
}
__device__ __forceinline__ uint32_t smem_u32p(const void* p) {
    uint32_t a;
    asm("{ .reg .u64 t; cvta.to.shared.u64 t, %1; cvt.u32.u64 %0, t; }" : "=r"(a) : "l"(p));
    return a;
}
__device__ __forceinline__ void cpa16(uint32_t dst, const void* src, int nbytes) {
    asm volatile("cp.async.cg.shared.global [%0], [%1], 16, %2;"
                 :: "r"(dst), "l"(src), "r"(nbytes));
}
#define CPA_COMMIT() asm volatile("cp.async.commit_group;" ::: "memory")
#define CPA_WAIT0()  asm volatile("cp.async.wait_group 0;" ::: "memory")

// split 2 fp32 -> packed bf16 hi pair + lo pair
__device__ __forceinline__ void cvt_split(float vx, float vy, uint32_t& hi, uint32_t& lo) {
    __nv_bfloat162 h2 = __float22bfloat162_rn(make_float2(vx, vy));
    hi = *(uint32_t*)&h2;
    float hx = __uint_as_float((hi & 0xFFFFu) << 16);
    float hy = __uint_as_float(hi & 0xFFFF0000u);
    __nv_bfloat162 l2 = __float22bfloat162_rn(make_float2(vx - hx, vy - hy));
    lo = *(uint32_t*)&l2;
}

#define TM     256
#define KC     64
#define A_STRF 72                        // fp32 per A smem row (64 + 8 pad), 288 B
#define A_STG  (256 * 288)               // 73728 B per stage
#define B_ROW  416                       // 104 u32 * 4 B per B smem row
#define B_HALF 13312                     // 32 rows * 416
#define B_STG  (2 * B_HALF)              // hi + lo
#define SM_A   0
#define SM_B   (2 * A_STG)               // 147456
#define SM_TOT (SM_B + 2 * B_STG)        // 200704

__global__ __launch_bounds__(512, 1) void k_gemm(const float* __restrict__ x, int N) {
    extern __shared__ char smem[];
    uint32_t sb = smem_u32p(smem);
    int tid = threadIdx.x, wid = tid >> 5, lane = tid & 31;
    int g = lane >> 2, tig = lane & 3;
    int warp_m = wid >> 1, warp_n = wid & 1;       // 8 x 2
    int row_w = warp_m * 32, col_w = warp_n * 48;
    int row0 = blockIdx.x * TM;

    float acc[2][6][4];
    #pragma unroll
    for (int a = 0; a < 2; a++)
        #pragma unroll
        for (int b = 0; b < 6; b++)
            #pragma unroll
            for (int c = 0; c < 4; c++) acc[a][b][c] = 0.0f;

    #define ISSUE_CHUNK(CH, STG) do {                                              \
        int _ch = (CH), _st = (STG);                                               \
        _Pragma("unroll")                                                          \
        for (int i = 0; i < 8; i++) {                                              \
            int p = tid + i * 512;                                                 \
            int row = p >> 4, cq = p & 15;                                         \
            int r = row0 + row;                                                    \
            int ok = (r < N) ? 16 : 0;                                             \
            int rc = (r < N) ? r : (N - 1);                                        \
            const float* src = &x[(size_t)rc * FDIM + _ch * KC + cq * 4];          \
            cpa16(sb + SM_A + _st * A_STG + row * 288 + cq * 16, src, ok);         \
        }                                                                          \
        _Pragma("unroll")                                                          \
        for (int i = 0; i < 3; i++) {                                              \
            int p = tid + i * 512;                                                 \
            int half = p >= 768;                                                   \
            int q = p - half * 768;                                                \
            int k2 = q / 24, c16 = q - k2 * 24;                                    \
            const uint32_t* src = (half ? g_WLt : g_WHt)                           \
                                  + (_ch * 32 + k2) * C3 + c16 * 4;                \
            cpa16(sb + SM_B + _st * B_STG + half * B_HALF + k2 * B_ROW + c16 * 16, \
                  src, 16);                                                        \
        }                                                                          \
        CPA_COMMIT();                                                              \
    } while (0)

    ISSUE_CHUNK(0, 0);

    const float* As;
    const uint32_t *Bhs, *Bls;
    for (int ch = 0; ch < FDIM / KC; ch++) {
        int st = ch & 1;
        CPA_WAIT0();
        __syncthreads();
        if (ch + 1 < FDIM / KC) ISSUE_CHUNK(ch + 1, (ch + 1) & 1);

        As  = (const float*)(smem + SM_A + st * A_STG);
        Bhs = (const uint32_t*)(smem + SM_B + st * B_STG);
        Bls = (const uint32_t*)(smem + SM_B + st * B_STG + B_HALF);

        #pragma unroll
        for (int kk = 0; kk < KC / 16; kk++) {
            int kb = kk * 16;
            uint32_t ah[2][4], al[2][4], bh[6][2], bl[6][2];
            #pragma unroll
            for (int mt = 0; mt < 2; mt++) {
                int r = row_w + mt * 16 + g;
                float2 v0 = *(const float2*)&As[r * A_STRF + kb + 2 * tig];
                float2 v1 = *(const float2*)&As[(r + 8) * A_STRF + kb + 2 * tig];
                float2 v2 = *(const float2*)&As[r * A_STRF + kb + 8 + 2 * tig];
                float2 v3 = *(const float2*)&As[(r + 8) * A_STRF + kb + 8 + 2 * tig];
                cvt_split(v0.x, v0.y, ah[mt][0], al[mt][0]);
                cvt_split(v1.x, v1.y, ah[mt][1], al[mt][1]);
                cvt_split(v2.x, v2.y, ah[mt][2], al[mt][2]);
                cvt_split(v3.x, v3.y, ah[mt][3], al[mt][3]);
            }
            #pragma unroll
            for (int nt = 0; nt < 6; nt++) {
                int c = col_w + nt * 8 + g;
                bh[nt][0] = Bhs[(kk * 8 + tig) * 104 + c];
                bh[nt][1] = Bhs[(kk * 8 + tig + 4) * 104 + c];
                bl[nt][0] = Bls[(kk * 8 + tig) * 104 + c];
                bl[nt][1] = Bls[(kk * 8 + tig + 4) * 104 + c];
            }
            #pragma unroll
            for (int mt = 0; mt < 2; mt++)
                #pragma unroll
                for (int nt = 0; nt < 6; nt++) {
                    mma16816(acc[mt][nt], ah[mt], bh[nt]);
                    mma16816(acc[mt][nt], ah[mt], bl[nt]);
                    mma16816(acc[mt][nt], al[mt], bh[nt]);
                }
        }
        __syncthreads();
    }

    #pragma unroll
    for (int mt = 0; mt < 2; mt++) {
        int r = row0 + row_w + mt * 16 + g;
        #pragma unroll
        for (int nt = 0; nt < 6; nt++) {
            int c = col_w + nt * 8 + 2 * tig;
            if (r < N)
                *(float2*)&g_H[(size_t)r * C3 + c] = make_float2(acc[mt][nt][0], acc[mt][nt][1]);
            if (r + 8 < N)
                *(float2*)&g_H[(size_t)(r + 8) * C3 + c] = make_float2(acc[mt][nt][2], acc[mt][nt][3]);
        }
    }
    #undef ISSUE_CHUNK
}

// ---------------- count only ----------------
__global__ void k_cnt(const void* ei, int E) {
    int e = blockIdx.x * blockDim.x + threadIdx.x;
    if (e >= E) return;
    int dst;
    if (g_is64) dst = (int)((const long long*)ei)[E + e];
    else        dst = ((const int*)ei)[E + e];
    atomicAdd(&g_cnt[dst], 1);
}

// ---------------- exclusive prefix sum of g_cnt -> g_off ----------------
__global__ void k_scan1(int N) {
    __shared__ int warpsum[16];
    int b = blockIdx.x, t = threadIdx.x;
    int i = b * 512 + t;
    int v = (i < N) ? g_cnt[i] : 0;
    int lane = t & 31, wid = t >> 5;
    int x = v;
    #pragma unroll
    for (int o = 1; o < 32; o <<= 1) {
        int y = __shfl_up_sync(0xFFFFFFFFu, x, o);
        if (lane >= o) x += y;
    }
    if (lane == 31) warpsum[wid] = x;
    __syncthreads();
    if (wid == 0) {
        int ws = (lane < 16) ? warpsum[lane] : 0;
        #pragma unroll
        for (int o = 1; o < 16; o <<= 1) {
            int y = __shfl_up_sync(0xFFFFFFFFu, ws, o);
            if (lane >= o) ws += y;
        }
        if (lane < 16) warpsum[lane] = ws;
    }
    __syncthreads();
    int base = (wid > 0) ? warpsum[wid - 1] : 0;
    if (i < N) g_off[i] = base + x - v;
    if (t == 511) g_bsum[b] = base + x;
}

__global__ void k_scan2(int NB) {
    __shared__ int sh[1024];
    int t = threadIdx.x;
    sh[t] = (t < NB) ? g_bsum[t] : 0;
    __syncthreads();
    for (int o = 1; o < 1024; o <<= 1) {
        int v = sh[t];
        int add = (t >= o) ? sh[t - o] : 0;
        __syncthreads();
        sh[t] = v + add;
        __syncthreads();
    }
    if (t < NB) g_bsum[t] = (t > 0) ? sh[t - 1] : 0;
}

__global__ void k_scan3(int N, int E) {
    int i = blockIdx.x * blockDim.x + threadIdx.x;
    if (i < N) {
        int o = g_off[i] + g_bsum[i >> 9];
        g_off[i] = o;
        g_cursor[i] = o;
    }
    if (i == 0) g_off[N] = E;
}

// ------- scatter edges into packed CSR: {w, src | m1bit<<30 | m2bit<<31} -------
__global__ void k_scatter(const void* ei, const float* __restrict__ w,
                          const float* __restrict__ m1, const float* __restrict__ m2, int E) {
    int e = blockIdx.x * blockDim.x + threadIdx.x;
    if (e >= E) return;
    int2 sd = read_edge(ei, E, e, g_is64);
    float we = w[e];
    unsigned int packed = (unsigned int)sd.x;
    if (m1[e] > 0.5f) packed |= 0x40000000u;
    if (m2[e] > 0.5f) packed |= 0x80000000u;
    int p = atomicAdd(&g_cursor[sd.y], 1);
    g_csr[p] = make_float2(we, __uint_as_float(packed));
}

// ---------------- degrees from CSR segments (no atomics), dinv ----------------
__global__ void k_deg2(int N) {
    int warp = (blockIdx.x * blockDim.x + threadIdx.x) >> 5;
    int lane = threadIdx.x & 31;
    if (warp >= N) return;
    int beg = g_off[warp], end = g_off[warp + 1];
    float s0 = 0.f, s1 = 0.f, s2 = 0.f;
    for (int p = beg + lane; p < end; p += 32) {
        float2 md = g_csr[p];
        unsigned int pk = __float_as_uint(md.y);
        s0 += md.x;
        if (pk & 0x40000000u) s1 += md.x;
        if (pk & 0x80000000u) s2 += md.x;
    }
    #pragma unroll
    for (int o = 16; o; o >>= 1) {
        s0 += __shfl_xor_sync(0xFFFFFFFFu, s0, o);
        s1 += __shfl_xor_sync(0xFFFFFFFFu, s1, o);
        s2 += __shfl_xor_sync(0xFFFFFFFFu, s2, o);
    }
    if (lane == 0) {
        g_dinv4[warp] = make_float4(rsqrtf(s0 + 1.0f), rsqrtf(s1 + 1.0f), rsqrtf(s2 + 1.0f), 0.f);
    }
}

// ---------------- scale H by dinv per view: H'[n][v*32+c] = H * dinv_v[n] ----------------
__global__ void k_scaleH(int N) {
    int warp = (blockIdx.x * blockDim.x + threadIdx.x) >> 5;
    int lane = threadIdx.x & 31;
    if (warp >= N) return;
    float4 dd = g_dinv4[warp];
    size_t o = (size_t)warp * C3;
    g_H[o + lane]      *= dd.x;
    g_H[o + lane + 32] *= dd.y;
    g_H[o + lane + 64] *= dd.z;
}

// ---- agg body over PRE-SCALED H': a_v = sum_e H'[src][v]·w_v(e), 8-wide gather MLP ----
__device__ __forceinline__ void agg_body(const float* __restrict__ Hsrc, int beg, int end,
                                         int lane, float& a0, float& a1, float& a2) {
    for (int base = beg; base < end; base += 32) {
        int cnt = end - base; if (cnt > 32) cnt = 32;
        // one coalesced load: 32 edges' metadata
        float2 md = (lane < cnt) ? g_csr[base + lane] : make_float2(0.f, 0.f);
        unsigned int pk = __float_as_uint(md.y);
        float w = md.x;
        int j = 0;
        #pragma unroll 1
        for (; j + 8 <= cnt; j += 8) {
            unsigned int pp[8];
            float ww[8];
            const float* hp[8];
            #pragma unroll
            for (int q = 0; q < 8; q++) {
                pp[q] = __shfl_sync(0xFFFFFFFFu, pk, j + q);
                ww[q] = __shfl_sync(0xFFFFFFFFu, w, j + q);
                hp[q] = &Hsrc[(size_t)(pp[q] & 0x3FFFFFFFu) * C3];
            }
            float v0[8], v1[8], v2[8];
            #pragma unroll
            for (int q = 0; q < 8; q++) {
                v0[q] = hp[q][lane];
                v1[q] = hp[q][lane + 32];
                v2[q] = hp[q][lane + 64];
            }
            #pragma unroll
            for (int q = 0; q < 8; q++) {
                a0 += v0[q] * ww[q];
                a1 += v1[q] * ((pp[q] & 0x40000000u) ? ww[q] : 0.f);
                a2 += v2[q] * ((pp[q] & 0x80000000u) ? ww[q] : 0.f);
            }
        }
        for (; j < cnt; j++) {
            unsigned int pj = __shfl_sync(0xFFFFFFFFu, pk, j);
            float wj = __shfl_sync(0xFFFFFFFFu, w, j);
            const float* hr = &Hsrc[(size_t)(pj & 0x3FFFFFFFu) * C3];
            a0 += hr[lane] * wj;
            a1 += hr[lane + 32] * ((pj & 0x40000000u) ? wj : 0.f);
            a2 += hr[lane + 64] * ((pj & 0x80000000u) ? wj : 0.f);
        }
    }
}

// ---- fused layer-1: agg + self + bias + relu + W2 matmul; writes PRE-SCALED H2' ----
__global__ void k_agg1mid(const float* __restrict__ b1, const float* __restrict__ W2, int N) {
    __shared__ float Ws[HID * HID];
    int t = threadIdx.x;
    for (int l = t; l < HID * HID; l += blockDim.x) Ws[l] = W2[l];
    __syncthreads();
    int warp = (blockIdx.x * blockDim.x + t) >> 5;
    int lane = t & 31;
    if (warp >= N) return;
    float4 dd = g_dinv4[warp];
    float a0 = 0.f, a1 = 0.f, a2 = 0.f;
    agg_body(g_H, g_off[warp], g_off[warp + 1], lane, a0, a1, a2);

    size_t o = (size_t)warp * C3;
    float bb = b1[lane];
    // z = dd*(a + H'[n]) + b  (H' already scaled by dinv)
    float z0 = fmaxf(dd.x * (a0 + g_H[o + lane])      + bb, 0.0f);
    float z1 = fmaxf(dd.y * (a1 + g_H[o + lane + 32]) + bb, 0.0f);
    float z2 = fmaxf(dd.z * (a2 + g_H[o + lane + 64]) + bb, 0.0f);
    float o0 = 0.f, o1 = 0.f, o2 = 0.f;
    #pragma unroll
    for (int k = 0; k < HID; k++) {
        float wv = Ws[k * HID + lane];
        o0 += __shfl_sync(0xFFFFFFFFu, z0, k) * wv;
        o1 += __shfl_sync(0xFFFFFFFFu, z1, k) * wv;
        o2 += __shfl_sync(0xFFFFFFFFu, z2, k) * wv;
    }
    // store pre-scaled for layer-2 gathers
    g_H2[o + lane]      = o0 * dd.x;
    g_H2[o + lane + 32] = o1 * dd.y;
    g_H2[o + lane + 64] = o2 * dd.z;
}

// ---- fused layer-2: agg + self + bias + relu + permute -> d_out ----
__global__ void k_agg2post(const float* __restrict__ b2, float* __restrict__ out, int N) {
    int warp = (blockIdx.x * blockDim.x + threadIdx.x) >> 5;
    int lane = threadIdx.x & 31;
    if (warp >= N) return;
    float4 dd = g_dinv4[warp];
    float a0 = 0.f, a1 = 0.f, a2 = 0.f;
    agg_body(g_H2, g_off[warp], g_off[warp + 1], lane, a0, a1, a2);

    size_t o = (size_t)warp * C3;
    float bb = b2[lane];
    float r0 = fmaxf(dd.x * (a0 + g_H2[o + lane])      + bb, 0.0f);
    float r1 = fmaxf(dd.y * (a1 + g_H2[o + lane + 32]) + bb, 0.0f);
    float r2 = fmaxf(dd.z * (a2 + g_H2[o + lane + 64]) + bb, 0.0f);
    out[((size_t)0 * N + warp) * HID + lane] = r0;
    out[((size_t)1 * N + warp) * HID + lane] = r1;
    out[((size_t)2 * N + warp) * HID + lane] = r2;
}

// =====================================================================
extern "C" void kernel_launch(void* const* d_in, const int* in_sizes, int n_in,
                              void* d_out, int out_size) {
    const float* x   = (const float*)d_in[0];
    const void*  ei  = d_in[1];
    const float* w   = (const float*)d_in[2];
    const float* m1  = (const float*)d_in[3];
    const float* m2  = (const float*)d_in[4];
    const float* fm1 = (const float*)d_in[5];
    const float* fm2 = (const float*)d_in[6];
    const float* W1  = (const float*)d_in[7];
    const float* b1  = (const float*)d_in[8];
    const float* W2  = (const float*)d_in[9];
    const float* b2  = (const float*)d_in[10];

    int E = in_sizes[2];
    int F = in_sizes[5];
    int N = in_sizes[0] / F;

    // lazily created host-side objects (first call = uncaptured correctness run)
    static cudaStream_t s2 = nullptr;
    static cudaEvent_t ev_fork = nullptr, ev_join = nullptr;
    static int attr_done = 0;
    if (!attr_done) {
        cudaFuncSetAttribute(k_gemm, cudaFuncAttributeMaxDynamicSharedMemorySize, SM_TOT);
        cudaStreamCreateWithFlags(&s2, cudaStreamNonBlocking);
        cudaEventCreateWithFlags(&ev_fork, cudaEventDisableTiming);
        cudaEventCreateWithFlags(&ev_join, cudaEventDisableTiming);
        attr_done = 1;
    }

    // ---- fork immediately; edge pipeline (incl. detect) on s2 ----
    cudaEventRecord(ev_fork, 0);
    cudaStreamWaitEvent(s2, ev_fork, 0);

    k_detect<<<1, 256, 0, s2>>>((const unsigned int*)ei, (long long)2 * E);
    k_init<<<(N + 255) / 256, 256, 0, s2>>>(N);
    k_cnt<<<(E + 255) / 256, 256, 0, s2>>>(ei, E);
    int NB = (N + 511) / 512;
    k_scan1<<<NB, 512, 0, s2>>>(N);
    k_scan2<<<1, 1024, 0, s2>>>(NB);
    k_scan3<<<(N + 511) / 512, 512, 0, s2>>>(N, E);
    k_scatter<<<(E + 255) / 256, 256, 0, s2>>>(ei, w, m1, m2, E);
    k_deg2<<<(int)(((long long)N * 32 + 255) / 256), 256, 0, s2>>>(N);
    cudaEventRecord(ev_join, s2);

    // ---- origin stream: GEMM chain (overlaps edge pipeline) ----
    k_wcat<<<(C3 * FDIM + 255) / 256, 256>>>(W1, fm1, fm2);
    k_gemm<<<(N + TM - 1) / TM, 512, SM_TOT>>>(x, N);

    // ---- join, scale H by dinv, then fused agg layers ----
    cudaStreamWaitEvent(0, ev_join, 0);
    int nwb = (int)(((long long)N * 32 + 255) / 256);
    k_scaleH<<<nwb, 256>>>(N);
    k_agg1mid<<<nwb, 256>>>(b1, W2, N);
    k_agg2post<<<nwb, 256>>>(b2, (float*)d_out, N);
}

// round 17
// speedup vs baseline: 1.5908x; 1.0625x over previous
#include <cuda_runtime.h>
#include <cuda_bf16.h>
#include <cstdint>

#define NMAX   100000
#define EMAX   3200000
#define FDIM   512
#define HID    32
#define C3     96          // 3 views * 32

// ---------------- device scratch (static: no allocation allowed) ----------------
__device__ int    g_is64;
__device__ float4 g_dinv4[NMAX];          // {d0,d1,d2,-} packed
__device__ int    g_cnt[NMAX];
__device__ int    g_off[NMAX + 1];
__device__ int    g_cursor[NMAX];
__device__ int    g_bsum[1024];
__device__ float2 g_csr[EMAX];            // {w, src | m1bit<<30 | m2bit<<31}
__device__ uint32_t g_WHt[(FDIM / 2) * C3];   // bf16-hi k-pairs, [k2][n]
__device__ uint32_t g_WLt[(FDIM / 2) * C3];   // bf16-lo k-pairs, [k2][n]
__device__ float  g_H[(size_t)NMAX * C3];     // layer-1 features (dinv-scaled after k_scaleH)
__device__ float  g_H2[(size_t)NMAX * C3];    // layer-2 features (written pre-scaled)

// ---------------- dtype sniff: int64 edge_index has all-zero high words ----------
__global__ void k_detect(const unsigned int* __restrict__ wbuf, long long nwords) {
    __shared__ int s;
    if (threadIdx.x == 0) s = 1;
    __syncthreads();
    int ok = 1;
    for (long long i = threadIdx.x; i < 2048; i += blockDim.x) {
        long long wi = 2 * i + 1;
        if (wi < nwords && wbuf[wi] != 0u) ok = 0;
    }
    if (!ok) atomicAnd(&s, 0);
    __syncthreads();
    if (threadIdx.x == 0) g_is64 = s;
}

__device__ __forceinline__ int2 read_edge(const void* ei, int E, int e, int is64) {
    if (is64) {
        const long long* p = (const long long*)ei;
        return make_int2((int)p[e], (int)p[E + e]);
    } else {
        const int* p = (const int*)ei;
        return make_int2(p[e], p[E + e]);
    }
}

__global__ void k_init(int N) {
    int i = blockIdx.x * blockDim.x + threadIdx.x;
    if (i < N) g_cnt[i] = 0;
}

// -------- fold feature masks into W1; bf16 hi/lo split, k-pair-packed [k2][n] --------
__global__ void k_wcat(const float* __restrict__ W1,
                       const float* __restrict__ fm1, const float* __restrict__ fm2) {
    int i = blockIdx.x * blockDim.x + threadIdx.x;
    if (i >= C3 * FDIM) return;
    int nn = i / FDIM, k = i - nn * FDIM;
    int v = nn >> 5, c = nn & 31;
    float m = (v == 0) ? 1.0f : (v == 1 ? fm1[k] : fm2[k]);
    float val = W1[k * HID + c] * m;
    __nv_bfloat16 h = __float2bfloat16(val);
    __nv_bfloat16 l = __float2bfloat16(val - __bfloat162float(h));
    int addr = ((k >> 1) * C3 + nn) * 2 + (k & 1);
    ((__nv_bfloat16*)g_WHt)[addr] = h;
    ((__nv_bfloat16*)g_WLt)[addr] = l;
}

// ======= HMMA GEMM, cp.async pipelined: H[N,96] = x[N,512] @ Wcat (3-term bf16 split) =======
__device__ __forceinline__ void mma16816(float* d, const uint32_t* a, const uint32_t* b) {
    asm volatile("mma.sync.aligned.m16n8k16.row.col.f32.bf16.bf16.f32 "
        "{%0,%1,%2,%3}, {%4,%5,%6,%7}, {%8,%9}, {%0,%1,%2,%3};"
        : "+f"(d[0]), "+f"(d[1]), "+f"(d[2]), "+f"(d[3])
        : "r"(a[0]), "r"(a[1]), "r"(a[2]), "r"(a[3]), "r"(b[0]), "r"(b[1]));
}
__device__ __forceinline__ uint32_t smem_u32p(const void* p) {
    uint32_t a;
    asm("{ .reg .u64 t; cvta.to.shared.u64 t, %1; cvt.u32.u64 %0, t; }" : "=r"(a) : "l"(p));
    return a;
}
__device__ __forceinline__ void cpa16(uint32_t dst, const void* src, int nbytes) {
    asm volatile("cp.async.cg.shared.global [%0], [%1], 16, %2;"
                 :: "r"(dst), "l"(src), "r"(nbytes));
}
#define CPA_COMMIT() asm volatile("cp.async.commit_group;" ::: "memory")
#define CPA_WAIT0()  asm volatile("cp.async.wait_group 0;" ::: "memory")

// split 2 fp32 -> packed bf16 hi pair + lo pair
__device__ __forceinline__ void cvt_split(float vx, float vy, uint32_t& hi, uint32_t& lo) {
    __nv_bfloat162 h2 = __float22bfloat162_rn(make_float2(vx, vy));
    hi = *(uint32_t*)&h2;
    float hx = __uint_as_float((hi & 0xFFFFu) << 16);
    float hy = __uint_as_float(hi & 0xFFFF0000u);
    __nv_bfloat162 l2 = __float22bfloat162_rn(make_float2(vx - hx, vy - hy));
    lo = *(uint32_t*)&l2;
}

#define TM     256
#define KC     64
#define A_STRF 72                        // fp32 per A smem row (64 + 8 pad), 288 B
#define A_STG  (256 * 288)               // 73728 B per stage
#define B_ROW  416                       // 104 u32 * 4 B per B smem row
#define B_HALF 13312                     // 32 rows * 416
#define B_STG  (2 * B_HALF)              // hi + lo
#define SM_A   0
#define SM_B   (2 * A_STG)               // 147456
#define SM_TOT (SM_B + 2 * B_STG)        // 200704

__global__ __launch_bounds__(512, 1) void k_gemm(const float* __restrict__ x, int N) {
    extern __shared__ char smem[];
    uint32_t sb = smem_u32p(smem);
    int tid = threadIdx.x, wid = tid >> 5, lane = tid & 31;
    int g = lane >> 2, tig = lane & 3;
    int warp_m = wid >> 1, warp_n = wid & 1;       // 8 x 2
    int row_w = warp_m * 32, col_w = warp_n * 48;
    int row0 = blockIdx.x * TM;

    float acc[2][6][4];
    #pragma unroll
    for (int a = 0; a < 2; a++)
        #pragma unroll
        for (int b = 0; b < 6; b++)
            #pragma unroll
            for (int c = 0; c < 4; c++) acc[a][b][c] = 0.0f;

    #define ISSUE_CHUNK(CH, STG) do {                                              \
        int _ch = (CH), _st = (STG);                                               \
        _Pragma("unroll")                                                          \
        for (int i = 0; i < 8; i++) {                                              \
            int p = tid + i * 512;                                                 \
            int row = p >> 4, cq = p & 15;                                         \
            int r = row0 + row;                                                    \
            int ok = (r < N) ? 16 : 0;                                             \
            int rc = (r < N) ? r : (N - 1);                                        \
            const float* src = &x[(size_t)rc * FDIM + _ch * KC + cq * 4];          \
            cpa16(sb + SM_A + _st * A_STG + row * 288 + cq * 16, src, ok);         \
        }                                                                          \
        _Pragma("unroll")                                                          \
        for (int i = 0; i < 3; i++) {                                              \
            int p = tid + i * 512;                                                 \
            int half = p >= 768;                                                   \
            int q = p - half * 768;                                                \
            int k2 = q / 24, c16 = q - k2 * 24;                                    \
            const uint32_t* src = (half ? g_WLt : g_WHt)                           \
                                  + (_ch * 32 + k2) * C3 + c16 * 4;                \
            cpa16(sb + SM_B + _st * B_STG + half * B_HALF + k2 * B_ROW + c16 * 16, \
                  src, 16);                                                        \
        }                                                                          \
        CPA_COMMIT();                                                              \
    } while (0)

    ISSUE_CHUNK(0, 0);

    const float* As;
    const uint32_t *Bhs, *Bls;
    for (int ch = 0; ch < FDIM / KC; ch++) {
        int st = ch & 1;
        CPA_WAIT0();
        __syncthreads();
        if (ch + 1 < FDIM / KC) ISSUE_CHUNK(ch + 1, (ch + 1) & 1);

        As  = (const float*)(smem + SM_A + st * A_STG);
        Bhs = (const uint32_t*)(smem + SM_B + st * B_STG);
        Bls = (const uint32_t*)(smem + SM_B + st * B_STG + B_HALF);

        #pragma unroll
        for (int kk = 0; kk < KC / 16; kk++) {
            int kb = kk * 16;
            uint32_t ah[2][4], al[2][4], bh[6][2], bl[6][2];
            #pragma unroll
            for (int mt = 0; mt < 2; mt++) {
                int r = row_w + mt * 16 + g;
                float2 v0 = *(const float2*)&As[r * A_STRF + kb + 2 * tig];
                float2 v1 = *(const float2*)&As[(r + 8) * A_STRF + kb + 2 * tig];
                float2 v2 = *(const float2*)&As[r * A_STRF + kb + 8 + 2 * tig];
                float2 v3 = *(const float2*)&As[(r + 8) * A_STRF + kb + 8 + 2 * tig];
                cvt_split(v0.x, v0.y, ah[mt][0], al[mt][0]);
                cvt_split(v1.x, v1.y, ah[mt][1], al[mt][1]);
                cvt_split(v2.x, v2.y, ah[mt][2], al[mt][2]);
                cvt_split(v3.x, v3.y, ah[mt][3], al[mt][3]);
            }
            #pragma unroll
            for (int nt = 0; nt < 6; nt++) {
                int c = col_w + nt * 8 + g;
                bh[nt][0] = Bhs[(kk * 8 + tig) * 104 + c];
                bh[nt][1] = Bhs[(kk * 8 + tig + 4) * 104 + c];
                bl[nt][0] = Bls[(kk * 8 + tig) * 104 + c];
                bl[nt][1] = Bls[(kk * 8 + tig + 4) * 104 + c];
            }
            #pragma unroll
            for (int mt = 0; mt < 2; mt++)
                #pragma unroll
                for (int nt = 0; nt < 6; nt++) {
                    mma16816(acc[mt][nt], ah[mt], bh[nt]);
                    mma16816(acc[mt][nt], ah[mt], bl[nt]);
                    mma16816(acc[mt][nt], al[mt], bh[nt]);
                }
        }
        __syncthreads();
    }

    #pragma unroll
    for (int mt = 0; mt < 2; mt++) {
        int r = row0 + row_w + mt * 16 + g;
        #pragma unroll
        for (int nt = 0; nt < 6; nt++) {
            int c = col_w + nt * 8 + 2 * tig;
            if (r < N)
                *(float2*)&g_H[(size_t)r * C3 + c] = make_float2(acc[mt][nt][0], acc[mt][nt][1]);
            if (r + 8 < N)
                *(float2*)&g_H[(size_t)(r + 8) * C3 + c] = make_float2(acc[mt][nt][2], acc[mt][nt][3]);
        }
    }
    #undef ISSUE_CHUNK
}

// ---------------- count only ----------------
__global__ void k_cnt(const void* ei, int E) {
    int e = blockIdx.x * blockDim.x + threadIdx.x;
    if (e >= E) return;
    int dst;
    if (g_is64) dst = (int)((const long long*)ei)[E + e];
    else        dst = ((const int*)ei)[E + e];
    atomicAdd(&g_cnt[dst], 1);
}

// ---------------- exclusive prefix sum of g_cnt -> g_off ----------------
__global__ void k_scan1(int N) {
    __shared__ int warpsum[16];
    int b = blockIdx.x, t = threadIdx.x;
    int i = b * 512 + t;
    int v = (i < N) ? g_cnt[i] : 0;
    int lane = t & 31, wid = t >> 5;
    int x = v;
    #pragma unroll
    for (int o = 1; o < 32; o <<= 1) {
        int y = __shfl_up_sync(0xFFFFFFFFu, x, o);
        if (lane >= o) x += y;
    }
    if (lane == 31) warpsum[wid] = x;
    __syncthreads();
    if (wid == 0) {
        int ws = (lane < 16) ? warpsum[lane] : 0;
        #pragma unroll
        for (int o = 1; o < 16; o <<= 1) {
            int y = __shfl_up_sync(0xFFFFFFFFu, ws, o);
            if (lane >= o) ws += y;
        }
        if (lane < 16) warpsum[lane] = ws;
    }
    __syncthreads();
    int base = (wid > 0) ? warpsum[wid - 1] : 0;
    if (i < N) g_off[i] = base + x - v;
    if (t == 511) g_bsum[b] = base + x;
}

__global__ void k_scan2(int NB) {
    __shared__ int sh[1024];
    int t = threadIdx.x;
    sh[t] = (t < NB) ? g_bsum[t] : 0;
    __syncthreads();
    for (int o = 1; o < 1024; o <<= 1) {
        int v = sh[t];
        int add = (t >= o) ? sh[t - o] : 0;
        __syncthreads();
        sh[t] = v + add;
        __syncthreads();
    }
    if (t < NB) g_bsum[t] = (t > 0) ? sh[t - 1] : 0;
}

__global__ void k_scan3(int N, int E) {
    int i = blockIdx.x * blockDim.x + threadIdx.x;
    if (i < N) {
        int o = g_off[i] + g_bsum[i >> 9];
        g_off[i] = o;
        g_cursor[i] = o;
    }
    if (i == 0) g_off[N] = E;
}

// ------- scatter edges into packed CSR: {w, src | m1bit<<30 | m2bit<<31} -------
__global__ void k_scatter(const void* ei, const float* __restrict__ w,
                          const float* __restrict__ m1, const float* __restrict__ m2, int E) {
    int e = blockIdx.x * blockDim.x + threadIdx.x;
    if (e >= E) return;
    int2 sd = read_edge(ei, E, e, g_is64);
    float we = w[e];
    unsigned int packed = (unsigned int)sd.x;
    if (m1[e] > 0.5f) packed |= 0x40000000u;
    if (m2[e] > 0.5f) packed |= 0x80000000u;
    int p = atomicAdd(&g_cursor[sd.y], 1);
    g_csr[p] = make_float2(we, __uint_as_float(packed));
}

// ---------------- degrees from CSR segments (no atomics), dinv ----------------
__global__ void k_deg2(int N) {
    int warp = (blockIdx.x * blockDim.x + threadIdx.x) >> 5;
    int lane = threadIdx.x & 31;
    if (warp >= N) return;
    int beg = g_off[warp], end = g_off[warp + 1];
    float s0 = 0.f, s1 = 0.f, s2 = 0.f;
    for (int p = beg + lane; p < end; p += 32) {
        float2 md = g_csr[p];
        unsigned int pk = __float_as_uint(md.y);
        s0 += md.x;
        if (pk & 0x40000000u) s1 += md.x;
        if (pk & 0x80000000u) s2 += md.x;
    }
    #pragma unroll
    for (int o = 16; o; o >>= 1) {
        s0 += __shfl_xor_sync(0xFFFFFFFFu, s0, o);
        s1 += __shfl_xor_sync(0xFFFFFFFFu, s1, o);
        s2 += __shfl_xor_sync(0xFFFFFFFFu, s2, o);
    }
    if (lane == 0) {
        g_dinv4[warp] = make_float4(rsqrtf(s0 + 1.0f), rsqrtf(s1 + 1.0f), rsqrtf(s2 + 1.0f), 0.f);
    }
}

// ---------------- scale H by dinv per view: H'[n][v*32+c] = H * dinv_v[n] ----------------
__global__ void k_scaleH(int N) {
    int warp = (blockIdx.x * blockDim.x + threadIdx.x) >> 5;
    int lane = threadIdx.x & 31;
    if (warp >= N) return;
    float4 dd = g_dinv4[warp];
    size_t o = (size_t)warp * C3;
    g_H[o + lane]      *= dd.x;
    g_H[o + lane + 32] *= dd.y;
    g_H[o + lane + 64] *= dd.z;
}

// ---- agg body over PRE-SCALED H': 4-wide MLP, mask-predicated view gathers ----
// Mask bits are warp-uniform per edge -> predicated-off rows issue no sectors.
__device__ __forceinline__ void agg_body(const float* __restrict__ Hsrc, int beg, int end,
                                         int lane, float& a0, float& a1, float& a2) {
    for (int base = beg; base < end; base += 32) {
        int cnt = end - base; if (cnt > 32) cnt = 32;
        // one coalesced load: 32 edges' metadata
        float2 md = (lane < cnt) ? g_csr[base + lane] : make_float2(0.f, 0.f);
        unsigned int pk = __float_as_uint(md.y);
        float w = md.x;
        int j = 0;
        #pragma unroll 1
        for (; j + 4 <= cnt; j += 4) {
            unsigned int p0 = __shfl_sync(0xFFFFFFFFu, pk, j);
            unsigned int p1 = __shfl_sync(0xFFFFFFFFu, pk, j + 1);
            unsigned int p2 = __shfl_sync(0xFFFFFFFFu, pk, j + 2);
            unsigned int p3 = __shfl_sync(0xFFFFFFFFu, pk, j + 3);
            float w0 = __shfl_sync(0xFFFFFFFFu, w, j);
            float w1 = __shfl_sync(0xFFFFFFFFu, w, j + 1);
            float w2 = __shfl_sync(0xFFFFFFFFu, w, j + 2);
            float w3 = __shfl_sync(0xFFFFFFFFu, w, j + 3);
            const float* h0 = &Hsrc[(size_t)(p0 & 0x3FFFFFFFu) * C3];
            const float* h1 = &Hsrc[(size_t)(p1 & 0x3FFFFFFFu) * C3];
            const float* h2 = &Hsrc[(size_t)(p2 & 0x3FFFFFFFu) * C3];
            const float* h3 = &Hsrc[(size_t)(p3 & 0x3FFFFFFFu) * C3];
            // view 0: always
            a0 += h0[lane] * w0 + h1[lane] * w1 + h2[lane] * w2 + h3[lane] * w3;
            // view 1: warp-uniform predicate, load skipped when edge removed
            if (p0 & 0x40000000u) a1 += h0[lane + 32] * w0;
            if (p1 & 0x40000000u) a1 += h1[lane + 32] * w1;
            if (p2 & 0x40000000u) a1 += h2[lane + 32] * w2;
            if (p3 & 0x40000000u) a1 += h3[lane + 32] * w3;
            // view 2
            if (p0 & 0x80000000u) a2 += h0[lane + 64] * w0;
            if (p1 & 0x80000000u) a2 += h1[lane + 64] * w1;
            if (p2 & 0x80000000u) a2 += h2[lane + 64] * w2;
            if (p3 & 0x80000000u) a2 += h3[lane + 64] * w3;
        }
        for (; j < cnt; j++) {
            unsigned int pj = __shfl_sync(0xFFFFFFFFu, pk, j);
            float wj = __shfl_sync(0xFFFFFFFFu, w, j);
            const float* hr = &Hsrc[(size_t)(pj & 0x3FFFFFFFu) * C3];
            a0 += hr[lane] * wj;
            if (pj & 0x40000000u) a1 += hr[lane + 32] * wj;
            if (pj & 0x80000000u) a2 += hr[lane + 64] * wj;
        }
    }
}

// ---- fused layer-1: agg + self + bias + relu + W2 matmul; writes PRE-SCALED H2' ----
__global__ void k_agg1mid(const float* __restrict__ b1, const float* __restrict__ W2, int N) {
    __shared__ float Ws[HID * HID];
    int t = threadIdx.x;
    for (int l = t; l < HID * HID; l += blockDim.x) Ws[l] = W2[l];
    __syncthreads();
    int warp = (blockIdx.x * blockDim.x + t) >> 5;
    int lane = t & 31;
    if (warp >= N) return;
    float4 dd = g_dinv4[warp];
    float a0 = 0.f, a1 = 0.f, a2 = 0.f;
    agg_body(g_H, g_off[warp], g_off[warp + 1], lane, a0, a1, a2);

    size_t o = (size_t)warp * C3;
    float bb = b1[lane];
    // z = dd*(a + H'[n]) + b  (H' already scaled by dinv)
    float z0 = fmaxf(dd.x * (a0 + g_H[o + lane])      + bb, 0.0f);
    float z1 = fmaxf(dd.y * (a1 + g_H[o + lane + 32]) + bb, 0.0f);
    float z2 = fmaxf(dd.z * (a2 + g_H[o + lane + 64]) + bb, 0.0f);
    float o0 = 0.f, o1 = 0.f, o2 = 0.f;
    #pragma unroll
    for (int k = 0; k < HID; k++) {
        float wv = Ws[k * HID + lane];
        o0 += __shfl_sync(0xFFFFFFFFu, z0, k) * wv;
        o1 += __shfl_sync(0xFFFFFFFFu, z1, k) * wv;
        o2 += __shfl_sync(0xFFFFFFFFu, z2, k) * wv;
    }
    // store pre-scaled for layer-2 gathers
    g_H2[o + lane]      = o0 * dd.x;
    g_H2[o + lane + 32] = o1 * dd.y;
    g_H2[o + lane + 64] = o2 * dd.z;
}

// ---- fused layer-2: agg + self + bias + relu + permute -> d_out ----
__global__ void k_agg2post(const float* __restrict__ b2, float* __restrict__ out, int N) {
    int warp = (blockIdx.x * blockDim.x + threadIdx.x) >> 5;
    int lane = threadIdx.x & 31;
    if (warp >= N) return;
    float4 dd = g_dinv4[warp];
    float a0 = 0.f, a1 = 0.f, a2 = 0.f;
    agg_body(g_H2, g_off[warp], g_off[warp + 1], lane, a0, a1, a2);

    size_t o = (size_t)warp * C3;
    float bb = b2[lane];
    float r0 = fmaxf(dd.x * (a0 + g_H2[o + lane])      + bb, 0.0f);
    float r1 = fmaxf(dd.y * (a1 + g_H2[o + lane + 32]) + bb, 0.0f);
    float r2 = fmaxf(dd.z * (a2 + g_H2[o + lane + 64]) + bb, 0.0f);
    out[((size_t)0 * N + warp) * HID + lane] = r0;
    out[((size_t)1 * N + warp) * HID + lane] = r1;
    out[((size_t)2 * N + warp) * HID + lane] = r2;
}

// =====================================================================
extern "C" void kernel_launch(void* const* d_in, const int* in_sizes, int n_in,
                              void* d_out, int out_size) {
    const float* x   = (const float*)d_in[0];
    const void*  ei  = d_in[1];
    const float* w   = (const float*)d_in[2];
    const float* m1  = (const float*)d_in[3];
    const float* m2  = (const float*)d_in[4];
    const float* fm1 = (const float*)d_in[5];
    const float* fm2 = (const float*)d_in[6];
    const float* W1  = (const float*)d_in[7];
    const float* b1  = (const float*)d_in[8];
    const float* W2  = (const float*)d_in[9];
    const float* b2  = (const float*)d_in[10];

    int E = in_sizes[2];
    int F = in_sizes[5];
    int N = in_sizes[0] / F;

    // lazily created host-side objects (first call = uncaptured correctness run)
    static cudaStream_t s2 = nullptr;
    static cudaEvent_t ev_fork = nullptr, ev_join = nullptr;
    static int attr_done = 0;
    if (!attr_done) {
        cudaFuncSetAttribute(k_gemm, cudaFuncAttributeMaxDynamicSharedMemorySize, SM_TOT);
        cudaStreamCreateWithFlags(&s2, cudaStreamNonBlocking);
        cudaEventCreateWithFlags(&ev_fork, cudaEventDisableTiming);
        cudaEventCreateWithFlags(&ev_join, cudaEventDisableTiming);
        attr_done = 1;
    }

    // ---- fork immediately; edge pipeline (incl. detect) on s2 ----
    cudaEventRecord(ev_fork, 0);
    cudaStreamWaitEvent(s2, ev_fork, 0);

    k_detect<<<1, 256, 0, s2>>>((const unsigned int*)ei, (long long)2 * E);
    k_init<<<(N + 255) / 256, 256, 0, s2>>>(N);
    k_cnt<<<(E + 255) / 256, 256, 0, s2>>>(ei, E);
    int NB = (N + 511) / 512;
    k_scan1<<<NB, 512, 0, s2>>>(N);
    k_scan2<<<1, 1024, 0, s2>>>(NB);
    k_scan3<<<(N + 511) / 512, 512, 0, s2>>>(N, E);
    k_scatter<<<(E + 255) / 256, 256, 0, s2>>>(ei, w, m1, m2, E);
    k_deg2<<<(int)(((long long)N * 32 + 255) / 256), 256, 0, s2>>>(N);
    cudaEventRecord(ev_join, s2);

    // ---- origin stream: GEMM chain (overlaps edge pipeline) ----
    k_wcat<<<(C3 * FDIM + 255) / 256, 256>>>(W1, fm1, fm2);
    k_gemm<<<(N + TM - 1) / TM, 512, SM_TOT>>>(x, N);

    // ---- join, scale H by dinv, then fused agg layers ----
    cudaStreamWaitEvent(0, ev_join, 0);
    int nwb = (int)(((long long)N * 32 + 255) / 256);
    k_scaleH<<<nwb, 256>>>(N);
    k_agg1mid<<<nwb, 256>>>(b1, W2, N);
    k_agg2post<<<nwb, 256>>>(b2, (float*)d_out, N);
}